// round 16
// baseline (speedup 1.0000x reference)
#include <cuda_runtime.h>
#include <cuda_fp16.h>
#include <cstdint>

// Problem constants
#define B_   32
#define NQ_  16384
#define NK_  31
#define DM_  64
#define H_   4

#define NTHREADS 256                     // 8 warps; each warp: 32 rows (2 m16 tiles)

// log2(e) / sqrt(d_head)
#define LOG2E_OVER_SCALE 0.36067376022224085f

// ---- smem layout ----
// VW4: [4h][2ch][4tg][66] uint4  (66 ≡ 2 mod 8 -> per-phase conflict-free LDS.128)
// K4 : [4h][4tg][34]     uint4  (34 ≡ 2 mod 8)
#define VW4_ENT 2112                     // (4*2*4)*66
#define OF_MO      10624                 // 32 floats
#define OF_BI      10656                 // 64 floats
#define OF_WB      10720                 // 8 warps x 2176 u32
#define WB_SIZE    2176
#define SMEM_U32   (10720 + 8 * 2176)    // 28128 u32 = 112512 B (2 CTAs/SM)

// per-warp buffer: TWO tiles of Q as half2 hi/lo [16][34] each (prefetched)
#define WB_QH(t) ((t) * 1088)
#define WB_QL(t) ((t) * 1088 + 544)
#define QPITCH 34

// Precomputed VW fragments: [b][2112] uint4 in the smem layout above
__device__ uint4 g_vw4[B_ * VW4_ENT];

// ---------------- helpers ----------------

__device__ __forceinline__ uint32_t f2h2(float a, float b) {
    __half2 h = __floats2half2_rn(a, b);
    return *(uint32_t*)&h;
}

// split (a,b) into packed half2 hi and exact-residual half2 lo (low half = a)
__device__ __forceinline__ void split2(float a, float b, uint32_t& hi, uint32_t& lo) {
    __half ha = __float2half_rn(a), hb = __float2half_rn(b);
    float la = a - __half2float(ha);
    float lb = b - __half2float(hb);
    __half2 hh = __halves2half2(ha, hb);
    hi = *(uint32_t*)&hh;
    lo = f2h2(la, lb);
}

__device__ __forceinline__ float ex2f(float x) {
    float y;
    asm("ex2.approx.ftz.f32 %0, %1;" : "=f"(y) : "f"(x));
    return y;
}
__device__ __forceinline__ float rcpf(float x) {
    float y;
    asm("rcp.approx.ftz.f32 %0, %1;" : "=f"(y) : "f"(x));
    return y;
}

// D += A(f16) * B(f16), m16n8k16, A row-major, B col-major, fp32 accumulate
__device__ __forceinline__ void mma_f16(float d[4],
                                        uint32_t a0, uint32_t a1,
                                        uint32_t a2, uint32_t a3,
                                        uint32_t b0, uint32_t b1) {
    asm volatile(
        "mma.sync.aligned.m16n8k16.row.col.f32.f16.f16.f32 "
        "{%0,%1,%2,%3}, {%4,%5,%6,%7}, {%8,%9}, {%0,%1,%2,%3};"
        : "+f"(d[0]), "+f"(d[1]), "+f"(d[2]), "+f"(d[3])
        : "r"(a0), "r"(a1), "r"(a2), "r"(a3), "r"(b0), "r"(b1));
}

// ===========================================================================
// Prep: build VW B-fragment uint4 table per batch.
// entry (h,ch,tg,n) = (hi(k0,k0+1), hi(k0+8,k0+9), lo(..), lo(..)),
//   k0 = 16ch + 2tg (key index within head).
// grid (B_, 16) x 128 threads, 1 entry per thread.
// ===========================================================================

__global__ void __launch_bounds__(128)
vw_prep(const float* __restrict__ V, const float* __restrict__ W)
{
    const int b = blockIdx.x;
    int r = blockIdx.y * 128 + threadIdx.x;       // 0..2047
    int n   = r & 63;
    int tgc = r >> 6;
    int tg  = tgc & 3;
    int ch  = (tgc >> 2) & 1;
    int h   = tgc >> 3;
    int k0  = 16 * ch + 2 * tg;

    const float* wp = W + n * DM_ + h * 16;
    float dd[4] = {0.f, 0.f, 0.f, 0.f};
    int keys[4] = {k0, k0 + 1, k0 + 8, k0 + 9};
#pragma unroll
    for (int j = 0; j < 4; j++) {
        if (keys[j] < NK_) {
            const float* vp = V + ((size_t)b * NK_ + keys[j]) * DM_ + h * 16;
            float acc = 0.f;
#pragma unroll
            for (int i = 0; i < 16; i++) acc += vp[i] * wp[i];
            dd[j] = acc;
        }
    }
    uint32_t h01, l01, h23, l23;
    split2(dd[0], dd[1], h01, l01);
    split2(dd[2], dd[3], h23, l23);
    g_vw4[b * VW4_ENT + ((h * 2 + ch) * 4 + tg) * 66 + n] =
        make_uint4(h01, h23, l01, l23);
}

// ===========================================================================
// Main (R15 structure + both-tile Q prefetch): per m16 tile -> per head:
// QK (fp16 3-term) -> softmax -> direct C->A frag convert -> GEMM2 (fp16
// 3-term). Direct STG.64 epilogue. Both Q tiles staged before the mainloop.
// ===========================================================================

__global__ void __launch_bounds__(NTHREADS, 2)
mha_tc_kernel(const float* __restrict__ Q,
              const float* __restrict__ K,
              const int* __restrict__ mask,
              const float* __restrict__ bias,
              float* __restrict__ out)
{
    extern __shared__ uint32_t smu[];
    float* sm = (float*)smu;
    uint4* sm4 = (uint4*)smu;
    const int tid  = threadIdx.x;
    const int wid  = tid >> 5;
    const int lane = tid & 31;
    const int g    = lane >> 2;      // groupID
    const int tg   = lane & 3;       // threadID in group
    const int b    = blockIdx.y;

    // ---------------- CTA staging ----------------
    {
        const uint4* src = g_vw4 + (size_t)b * VW4_ENT;
        for (int i = tid; i < VW4_ENT; i += NTHREADS) sm4[i] = src[i];

        // K fragment table: entry (h,tg,key) =
        //   (hi(K[key][16h+2tg],+1), hi(K[key][16h+2tg+8],+9), lo.., lo..)
        const float* Kb = K + (size_t)b * NK_ * DM_;
        for (int i = tid; i < 512; i += NTHREADS) {
            int hh  = i >> 7;
            int rem = i & 127;
            int tt  = rem >> 5;
            int key = rem & 31;
            float f0 = 0.f, f1 = 0.f, f2 = 0.f, f3 = 0.f;
            if (key < NK_) {
                const float* kp = Kb + (size_t)key * DM_ + 16 * hh + 2 * tt;
                f0 = kp[0]; f1 = kp[1]; f2 = kp[8]; f3 = kp[9];
            }
            uint32_t h01, l01, h23, l23;
            split2(f0, f1, h01, l01);
            split2(f2, f3, h23, l23);
            sm4[2112 + (hh * 4 + tt) * 34 + key] = make_uint4(h01, h23, l01, l23);
        }
        if (tid < 32)
            sm[OF_MO + tid] = (tid < NK_ && mask[b * NK_ + tid] != 0) ? 0.f : -1e30f;
        if (tid < DM_)
            sm[OF_BI + tid] = bias[tid];
    }
    __syncthreads();

    // per-lane mask-init values for the 4 QK n-tiles (C cols 2tg, 2tg+1)
    float mo0[4], mo1[4];
#pragma unroll
    for (int nt = 0; nt < 4; nt++) {
        mo0[nt] = sm[OF_MO + nt * 8 + 2 * tg];
        mo1[nt] = sm[OF_MO + nt * 8 + 2 * tg + 1];
    }

    uint32_t* wb = smu + OF_WB + wid * WB_SIZE;
    const int rowbase = blockIdx.x * 256 + wid * 32;   // tile t covers +t*16

    // ---- prefetch BOTH Q tiles (16x64 each): coalesced LDG.128 -> hi/lo ----
#pragma unroll
    for (int t = 0; t < 2; t++) {
        const float* Qt = Q + ((size_t)b * NQ_ + rowbase + t * 16) * DM_;
#pragma unroll
        for (int i = 0; i < 8; i++) {
            int idx = i * 32 + lane;
            int row = idx >> 4;
            int c4  = idx & 15;
            float4 v = *(const float4*)(Qt + (size_t)row * DM_ + c4 * 4);
            uint32_t h0, l0, h1, l1;
            split2(v.x, v.y, h0, l0);
            split2(v.z, v.w, h1, l1);
            *(uint2*)&wb[WB_QH(t) + row * QPITCH + 2 * c4] = make_uint2(h0, h1);
            *(uint2*)&wb[WB_QL(t) + row * QPITCH + 2 * c4] = make_uint2(l0, l1);
        }
    }
    __syncwarp();

#pragma unroll 1
    for (int t = 0; t < 2; t++) {
        // output accumulators: 8 n-tiles x m16n8 C fragments
        float d[8][4];
#pragma unroll
        for (int nt = 0; nt < 8; nt++) {
            d[nt][0] = 0.f; d[nt][1] = 0.f; d[nt][2] = 0.f; d[nt][3] = 0.f;
        }

#pragma unroll
        for (int h = 0; h < 4; h++) {
            // ---- Q A-fragments (packed half2 hi/lo) from warp buffer ----
            uint32_t ah[4], al[4];
            {
                int c2 = h * 8 + tg;
                ah[0] = wb[WB_QH(t) + g * QPITCH + c2];
                ah[1] = wb[WB_QH(t) + (g + 8) * QPITCH + c2];
                ah[2] = wb[WB_QH(t) + g * QPITCH + c2 + 4];
                ah[3] = wb[WB_QH(t) + (g + 8) * QPITCH + c2 + 4];
                al[0] = wb[WB_QL(t) + g * QPITCH + c2];
                al[1] = wb[WB_QL(t) + (g + 8) * QPITCH + c2];
                al[2] = wb[WB_QL(t) + g * QPITCH + c2 + 4];
                al[3] = wb[WB_QL(t) + (g + 8) * QPITCH + c2 + 4];
            }

            // ---- QK: one k16 per head, 3-term fp16, C seeded with mask ----
            float c[4][4];
#pragma unroll
            for (int nt = 0; nt < 4; nt++) {
                c[nt][0] = mo0[nt]; c[nt][1] = mo1[nt];
                c[nt][2] = mo0[nt]; c[nt][3] = mo1[nt];
            }
#pragma unroll
            for (int nt = 0; nt < 4; nt++) {
                uint4 kv = sm4[2112 + (h * 4 + tg) * 34 + nt * 8 + g];
                mma_f16(c[nt], ah[0], ah[1], ah[2], ah[3], kv.x, kv.y);
                mma_f16(c[nt], ah[0], ah[1], ah[2], ah[3], kv.z, kv.w);
                mma_f16(c[nt], al[0], al[1], al[2], al[3], kv.x, kv.y);
            }

            // ---- softmax on C fragments (rows g, g+8) ----
            float e[4][4];
            float sA = 0.f, sB = 0.f;
#pragma unroll
            for (int nt = 0; nt < 4; nt++) {
                e[nt][0] = ex2f(c[nt][0] * LOG2E_OVER_SCALE);
                e[nt][1] = ex2f(c[nt][1] * LOG2E_OVER_SCALE);
                e[nt][2] = ex2f(c[nt][2] * LOG2E_OVER_SCALE);
                e[nt][3] = ex2f(c[nt][3] * LOG2E_OVER_SCALE);
                sA += e[nt][0] + e[nt][1];
                sB += e[nt][2] + e[nt][3];
            }
            sA += __shfl_xor_sync(0xffffffffu, sA, 1);
            sA += __shfl_xor_sync(0xffffffffu, sA, 2);
            sB += __shfl_xor_sync(0xffffffffu, sB, 1);
            sB += __shfl_xor_sync(0xffffffffu, sB, 2);
            float rsA = (sA > 0.f) ? rcpf(sA) : 0.f;   // all-masked -> P = 0
            float rsB = (sB > 0.f) ? rcpf(sB) : 0.f;

            // ---- P: direct C->A fragment conversion (no smem round trip) ----
            // chunk ch A-frags come from n-tiles 2ch (a0,a1) and 2ch+1 (a2,a3)
            uint32_t ph[2][4], pl[2][4];
#pragma unroll
            for (int ch = 0; ch < 2; ch++) {
                split2(e[2*ch][0]   * rsA, e[2*ch][1]   * rsA, ph[ch][0], pl[ch][0]);
                split2(e[2*ch][2]   * rsB, e[2*ch][3]   * rsB, ph[ch][1], pl[ch][1]);
                split2(e[2*ch+1][0] * rsA, e[2*ch+1][1] * rsA, ph[ch][2], pl[ch][2]);
                split2(e[2*ch+1][2] * rsB, e[2*ch+1][3] * rsB, ph[ch][3], pl[ch][3]);
            }

            // ---- GEMM2: D += P_h @ VW_h, two k16 chunks, 3-term fp16 ----
#pragma unroll
            for (int ch = 0; ch < 2; ch++) {
#pragma unroll
                for (int nt = 0; nt < 8; nt++) {
                    uint4 wv = sm4[((h * 2 + ch) * 4 + tg) * 66 + nt * 8 + g];
                    mma_f16(d[nt], ph[ch][0], ph[ch][1], ph[ch][2], ph[ch][3],
                            wv.x, wv.y);
                    mma_f16(d[nt], ph[ch][0], ph[ch][1], ph[ch][2], ph[ch][3],
                            wv.z, wv.w);
                    mma_f16(d[nt], pl[ch][0], pl[ch][1], pl[ch][2], pl[ch][3],
                            wv.x, wv.y);
                }
            }
        }

        // ---- epilogue: direct STG.64 from fragments (32B sector-aligned) ----
        float* og = out + ((size_t)b * NQ_ + rowbase + t * 16) * DM_;
#pragma unroll
        for (int nt = 0; nt < 8; nt++) {
            float2 bb = *(const float2*)&sm[OF_BI + nt * 8 + 2 * tg];
            *(float2*)&og[(size_t)g * DM_ + nt * 8 + 2 * tg] =
                make_float2(d[nt][0] + bb.x, d[nt][1] + bb.y);
            *(float2*)&og[(size_t)(g + 8) * DM_ + nt * 8 + 2 * tg] =
                make_float2(d[nt][2] + bb.x, d[nt][3] + bb.y);
        }
    }
}

// ---------------------------------------------------------------------------

extern "C" void kernel_launch(void* const* d_in, const int* in_sizes, int n_in,
                              void* d_out, int out_size)
{
    const float* Q    = (const float*)d_in[0];
    const float* K    = (const float*)d_in[1];
    const float* V    = (const float*)d_in[2];
    const int*   mask = (const int*)d_in[3];
    const float* W    = (const float*)d_in[4];
    const float* bias = (const float*)d_in[5];
    float*       out  = (float*)d_out;

    static bool attr_set = false;
    if (!attr_set) {
        cudaFuncSetAttribute(mha_tc_kernel,
                             cudaFuncAttributeMaxDynamicSharedMemorySize,
                             SMEM_U32 * 4);
        attr_set = true;
    }

    dim3 gridP(B_, 16);
    vw_prep<<<gridP, 128>>>(V, W);

    dim3 grid(NQ_ / 256, B_);
    mha_tc_kernel<<<grid, NTHREADS, SMEM_U32 * 4>>>(Q, K, mask, bias, out);
}

// round 17
// speedup vs baseline: 1.0479x; 1.0479x over previous
#include <cuda_runtime.h>
#include <cuda_fp16.h>
#include <cstdint>

// Problem constants
#define B_   32
#define NQ_  16384
#define NK_  31
#define DM_  64
#define H_   4

#define NTHREADS 256                     // 8 warps; each warp: 32 rows (2 m16 tiles)

// log2(e) / sqrt(d_head)
#define LOG2E_OVER_SCALE 0.36067376022224085f

// ---- smem layout ----
// VW4: [4h][2ch][4tg][66] uint4  (66 ≡ 2 mod 8 -> per-phase conflict-free LDS.128)
// K4 : [4h][4tg][34]     uint4  (34 ≡ 2 mod 8)
#define VW4_ENT 2112                     // (4*2*4)*66
#define OF_MO      10624                 // 32 floats
#define OF_BI      10656                 // 64 floats
#define OF_WB      10720                 // 8 warps x 1152 u32
#define WB_SIZE    1152
#define SMEM_U32   (10720 + 8 * 1152)    // 19936 u32 = 79744 B (2 CTAs/SM)

// per-warp buffer: Q hi [16][36], Q lo [16][36] (one tile at a time)
#define WB_QH 0
#define WB_QL 576
#define QPITCH 36

// Precomputed VW fragments: [b][2112] uint4 in the smem layout above
__device__ uint4 g_vw4[B_ * VW4_ENT];

// ---------------- helpers ----------------

__device__ __forceinline__ uint32_t f2h2(float a, float b) {
    __half2 h = __floats2half2_rn(a, b);
    return *(uint32_t*)&h;
}

// split (a,b) into packed half2 hi and exact-residual half2 lo (low half = a)
__device__ __forceinline__ void split2(float a, float b, uint32_t& hi, uint32_t& lo) {
    __half ha = __float2half_rn(a), hb = __float2half_rn(b);
    float la = a - __half2float(ha);
    float lb = b - __half2float(hb);
    __half2 hh = __halves2half2(ha, hb);
    hi = *(uint32_t*)&hh;
    lo = f2h2(la, lb);
}

__device__ __forceinline__ float ex2f(float x) {
    float y;
    asm("ex2.approx.ftz.f32 %0, %1;" : "=f"(y) : "f"(x));
    return y;
}
__device__ __forceinline__ float rcpf(float x) {
    float y;
    asm("rcp.approx.ftz.f32 %0, %1;" : "=f"(y) : "f"(x));
    return y;
}

// streaming (evict-first) 8-byte global store: output is write-once dead data
__device__ __forceinline__ void stg_cs_v2(float* p, float x, float y) {
    asm volatile("st.global.cs.v2.f32 [%0], {%1, %2};"
                 :: "l"(p), "f"(x), "f"(y) : "memory");
}

// D += A(f16) * B(f16), m16n8k16, A row-major, B col-major, fp32 accumulate
__device__ __forceinline__ void mma_f16(float d[4],
                                        uint32_t a0, uint32_t a1,
                                        uint32_t a2, uint32_t a3,
                                        uint32_t b0, uint32_t b1) {
    asm volatile(
        "mma.sync.aligned.m16n8k16.row.col.f32.f16.f16.f32 "
        "{%0,%1,%2,%3}, {%4,%5,%6,%7}, {%8,%9}, {%0,%1,%2,%3};"
        : "+f"(d[0]), "+f"(d[1]), "+f"(d[2]), "+f"(d[3])
        : "r"(a0), "r"(a1), "r"(a2), "r"(a3), "r"(b0), "r"(b1));
}

// ===========================================================================
// Prep: build VW B-fragment uint4 table per batch.
// entry (h,ch,tg,n) = (hi(k0,k0+1), hi(k0+8,k0+9), lo(..), lo(..)),
//   k0 = 16ch + 2tg (key index within head).
// grid (B_, 16) x 128 threads, 1 entry per thread.
// ===========================================================================

__global__ void __launch_bounds__(128)
vw_prep(const float* __restrict__ V, const float* __restrict__ W)
{
    const int b = blockIdx.x;
    int r = blockIdx.y * 128 + threadIdx.x;       // 0..2047
    int n   = r & 63;
    int tgc = r >> 6;
    int tg  = tgc & 3;
    int ch  = (tgc >> 2) & 1;
    int h   = tgc >> 3;
    int k0  = 16 * ch + 2 * tg;

    const float* wp = W + n * DM_ + h * 16;
    float dd[4] = {0.f, 0.f, 0.f, 0.f};
    int keys[4] = {k0, k0 + 1, k0 + 8, k0 + 9};
#pragma unroll
    for (int j = 0; j < 4; j++) {
        if (keys[j] < NK_) {
            const float* vp = V + ((size_t)b * NK_ + keys[j]) * DM_ + h * 16;
            float acc = 0.f;
#pragma unroll
            for (int i = 0; i < 16; i++) acc += vp[i] * wp[i];
            dd[j] = acc;
        }
    }
    uint32_t h01, l01, h23, l23;
    split2(dd[0], dd[1], h01, l01);
    split2(dd[2], dd[3], h23, l23);
    g_vw4[b * VW4_ENT + ((h * 2 + ch) * 4 + tg) * 66 + n] =
        make_uint4(h01, h23, l01, l23);
}

// ===========================================================================
// Main (R15 structure): per m16 tile -> per head: QK (fp16 3-term) -> softmax
// -> direct C->A frag convert -> GEMM2 (fp16 3-term). Direct STG epilogue
// with streaming (evict-first) stores.
// ===========================================================================

__global__ void __launch_bounds__(NTHREADS, 2)
mha_tc_kernel(const float* __restrict__ Q,
              const float* __restrict__ K,
              const int* __restrict__ mask,
              const float* __restrict__ bias,
              float* __restrict__ out)
{
    extern __shared__ uint32_t smu[];
    float* sm = (float*)smu;
    uint4* sm4 = (uint4*)smu;
    const int tid  = threadIdx.x;
    const int wid  = tid >> 5;
    const int lane = tid & 31;
    const int g    = lane >> 2;      // groupID
    const int tg   = lane & 3;       // threadID in group
    const int b    = blockIdx.y;

    // ---------------- CTA staging ----------------
    {
        const uint4* src = g_vw4 + (size_t)b * VW4_ENT;
        for (int i = tid; i < VW4_ENT; i += NTHREADS) sm4[i] = src[i];

        // K fragment table: entry (h,tg,key) =
        //   (hi(K[key][16h+2tg],+1), hi(K[key][16h+2tg+8],+9), lo.., lo..)
        const float* Kb = K + (size_t)b * NK_ * DM_;
        for (int i = tid; i < 512; i += NTHREADS) {
            int hh  = i >> 7;
            int rem = i & 127;
            int tt  = rem >> 5;
            int key = rem & 31;
            float f0 = 0.f, f1 = 0.f, f2 = 0.f, f3 = 0.f;
            if (key < NK_) {
                const float* kp = Kb + (size_t)key * DM_ + 16 * hh + 2 * tt;
                f0 = kp[0]; f1 = kp[1]; f2 = kp[8]; f3 = kp[9];
            }
            uint32_t h01, l01, h23, l23;
            split2(f0, f1, h01, l01);
            split2(f2, f3, h23, l23);
            sm4[2112 + (hh * 4 + tt) * 34 + key] = make_uint4(h01, h23, l01, l23);
        }
        if (tid < 32)
            sm[OF_MO + tid] = (tid < NK_ && mask[b * NK_ + tid] != 0) ? 0.f : -1e30f;
        if (tid < DM_)
            sm[OF_BI + tid] = bias[tid];
    }
    __syncthreads();

    // per-lane mask-init values for the 4 QK n-tiles (C cols 2tg, 2tg+1)
    float mo0[4], mo1[4];
#pragma unroll
    for (int nt = 0; nt < 4; nt++) {
        mo0[nt] = sm[OF_MO + nt * 8 + 2 * tg];
        mo1[nt] = sm[OF_MO + nt * 8 + 2 * tg + 1];
    }

    uint32_t* wb = smu + OF_WB + wid * WB_SIZE;
    const int rowbase = blockIdx.x * 256 + wid * 32;   // tile t covers +t*16

#pragma unroll 1
    for (int t = 0; t < 2; t++) {
        const float* Qt = Q + ((size_t)b * NQ_ + rowbase + t * 16) * DM_;

        // ---- stage Q tile (16x64): coalesced LDG.128, split to half2 hi/lo ----
#pragma unroll
        for (int i = 0; i < 8; i++) {
            int idx = i * 32 + lane;
            int row = idx >> 4;
            int c4  = idx & 15;
            float4 v = *(const float4*)(Qt + (size_t)row * DM_ + c4 * 4);
            uint32_t h0, l0, h1, l1;
            split2(v.x, v.y, h0, l0);
            split2(v.z, v.w, h1, l1);
            *(uint2*)&wb[WB_QH + row * QPITCH + 2 * c4] = make_uint2(h0, h1);
            *(uint2*)&wb[WB_QL + row * QPITCH + 2 * c4] = make_uint2(l0, l1);
        }
        __syncwarp();

        // output accumulators: 8 n-tiles x m16n8 C fragments
        float d[8][4];
#pragma unroll
        for (int nt = 0; nt < 8; nt++) {
            d[nt][0] = 0.f; d[nt][1] = 0.f; d[nt][2] = 0.f; d[nt][3] = 0.f;
        }

#pragma unroll
        for (int h = 0; h < 4; h++) {
            // ---- Q A-fragments (packed half2 hi/lo) from warp buffer ----
            uint32_t ah[4], al[4];
            {
                int c2 = h * 8 + tg;
                ah[0] = wb[WB_QH + g * QPITCH + c2];
                ah[1] = wb[WB_QH + (g + 8) * QPITCH + c2];
                ah[2] = wb[WB_QH + g * QPITCH + c2 + 4];
                ah[3] = wb[WB_QH + (g + 8) * QPITCH + c2 + 4];
                al[0] = wb[WB_QL + g * QPITCH + c2];
                al[1] = wb[WB_QL + (g + 8) * QPITCH + c2];
                al[2] = wb[WB_QL + g * QPITCH + c2 + 4];
                al[3] = wb[WB_QL + (g + 8) * QPITCH + c2 + 4];
            }

            // ---- QK: one k16 per head, 3-term fp16, C seeded with mask ----
            float c[4][4];
#pragma unroll
            for (int nt = 0; nt < 4; nt++) {
                c[nt][0] = mo0[nt]; c[nt][1] = mo1[nt];
                c[nt][2] = mo0[nt]; c[nt][3] = mo1[nt];
            }
#pragma unroll
            for (int nt = 0; nt < 4; nt++) {
                uint4 kv = sm4[2112 + (h * 4 + tg) * 34 + nt * 8 + g];
                mma_f16(c[nt], ah[0], ah[1], ah[2], ah[3], kv.x, kv.y);
                mma_f16(c[nt], ah[0], ah[1], ah[2], ah[3], kv.z, kv.w);
                mma_f16(c[nt], al[0], al[1], al[2], al[3], kv.x, kv.y);
            }

            // ---- softmax on C fragments (rows g, g+8) ----
            float e[4][4];
            float sA = 0.f, sB = 0.f;
#pragma unroll
            for (int nt = 0; nt < 4; nt++) {
                e[nt][0] = ex2f(c[nt][0] * LOG2E_OVER_SCALE);
                e[nt][1] = ex2f(c[nt][1] * LOG2E_OVER_SCALE);
                e[nt][2] = ex2f(c[nt][2] * LOG2E_OVER_SCALE);
                e[nt][3] = ex2f(c[nt][3] * LOG2E_OVER_SCALE);
                sA += e[nt][0] + e[nt][1];
                sB += e[nt][2] + e[nt][3];
            }
            sA += __shfl_xor_sync(0xffffffffu, sA, 1);
            sA += __shfl_xor_sync(0xffffffffu, sA, 2);
            sB += __shfl_xor_sync(0xffffffffu, sB, 1);
            sB += __shfl_xor_sync(0xffffffffu, sB, 2);
            float rsA = (sA > 0.f) ? rcpf(sA) : 0.f;   // all-masked -> P = 0
            float rsB = (sB > 0.f) ? rcpf(sB) : 0.f;

            // ---- P: direct C->A fragment conversion (no smem round trip) ----
            // chunk ch A-frags come from n-tiles 2ch (a0,a1) and 2ch+1 (a2,a3)
            uint32_t ph[2][4], pl[2][4];
#pragma unroll
            for (int ch = 0; ch < 2; ch++) {
                split2(e[2*ch][0]   * rsA, e[2*ch][1]   * rsA, ph[ch][0], pl[ch][0]);
                split2(e[2*ch][2]   * rsB, e[2*ch][3]   * rsB, ph[ch][1], pl[ch][1]);
                split2(e[2*ch+1][0] * rsA, e[2*ch+1][1] * rsA, ph[ch][2], pl[ch][2]);
                split2(e[2*ch+1][2] * rsB, e[2*ch+1][3] * rsB, ph[ch][3], pl[ch][3]);
            }

            // ---- GEMM2: D += P_h @ VW_h, two k16 chunks, 3-term fp16 ----
#pragma unroll
            for (int ch = 0; ch < 2; ch++) {
#pragma unroll
                for (int nt = 0; nt < 8; nt++) {
                    uint4 wv = sm4[((h * 2 + ch) * 4 + tg) * 66 + nt * 8 + g];
                    mma_f16(d[nt], ph[ch][0], ph[ch][1], ph[ch][2], ph[ch][3],
                            wv.x, wv.y);
                    mma_f16(d[nt], ph[ch][0], ph[ch][1], ph[ch][2], ph[ch][3],
                            wv.z, wv.w);
                    mma_f16(d[nt], pl[ch][0], pl[ch][1], pl[ch][2], pl[ch][3],
                            wv.x, wv.y);
                }
            }
        }

        // ---- epilogue: direct streaming STG.64 (32B sector-aligned) ----
        float* og = out + ((size_t)b * NQ_ + rowbase + t * 16) * DM_;
#pragma unroll
        for (int nt = 0; nt < 8; nt++) {
            float2 bb = *(const float2*)&sm[OF_BI + nt * 8 + 2 * tg];
            stg_cs_v2(&og[(size_t)g * DM_ + nt * 8 + 2 * tg],
                      d[nt][0] + bb.x, d[nt][1] + bb.y);
            stg_cs_v2(&og[(size_t)(g + 8) * DM_ + nt * 8 + 2 * tg],
                      d[nt][2] + bb.x, d[nt][3] + bb.y);
        }
        __syncwarp();      // Q frag reads done before next tile's staging
    }
}

// ---------------------------------------------------------------------------

extern "C" void kernel_launch(void* const* d_in, const int* in_sizes, int n_in,
                              void* d_out, int out_size)
{
    const float* Q    = (const float*)d_in[0];
    const float* K    = (const float*)d_in[1];
    const float* V    = (const float*)d_in[2];
    const int*   mask = (const int*)d_in[3];
    const float* W    = (const float*)d_in[4];
    const float* bias = (const float*)d_in[5];
    float*       out  = (float*)d_out;

    static bool attr_set = false;
    if (!attr_set) {
        cudaFuncSetAttribute(mha_tc_kernel,
                             cudaFuncAttributeMaxDynamicSharedMemorySize,
                             SMEM_U32 * 4);
        attr_set = true;
    }

    dim3 gridP(B_, 16);
    vw_prep<<<gridP, 128>>>(V, W);

    dim3 grid(NQ_ / 256, B_);
    mha_tc_kernel<<<grid, NTHREADS, SMEM_U32 * 4>>>(Q, K, mask, bias, out);
}